// round 2
// baseline (speedup 1.0000x reference)
#include <cuda_runtime.h>
#include <math.h>

#define NN 50000
#define NE 800000
#define NT 850000     // NE + NN self loops
#define NGRAPH 512
#define NCLS 120

// ---------------- device scratch (no allocations allowed) ----------------
__device__ float g_h1[(size_t)NN * 256];    // layer1 features / reused for layer2 h2 (N x 64)
__device__ float g_x2[(size_t)NN * 256];    // elu output of layer1
__device__ float g_out2[(size_t)NN * 64];   // layer2 output
__device__ float g_als[NN * 4];
__device__ float g_ald[NN * 4];
__device__ float g_escr[(size_t)NT * 4];    // per-edge logits scratch
__device__ int   g_deg[NN];
__device__ int   g_starts[NN + 1];
__device__ int   g_cursor[NN];
__device__ int   g_srcs[NT];
__device__ float g_pool[NGRAPH * 64];
__device__ float g_cnt[NGRAPH];

// ---------------- utility ----------------
__global__ void zero_kernel() {
    int i = blockIdx.x * blockDim.x + threadIdx.x;
    if (i < NN) g_deg[i] = 0;
    if (i < NGRAPH * 64) g_pool[i] = 0.f;
    if (i < NGRAPH) g_cnt[i] = 0.f;
}

// ---------------- tiled GEMM: C[NN x ldb] = A[NN x K] @ B[K x ldb] ----------------
__device__ __forceinline__ void gemm_body(const float* __restrict__ A,
                                          const float* __restrict__ B,
                                          float* __restrict__ C,
                                          int K, int ldb) {
    __shared__ float xs[64][65];
    __shared__ float ws[64][65];
    int row0 = blockIdx.x * 64;
    int col0 = blockIdx.y * 64;
    int tid = threadIdx.x;        // 256 threads
    int tr = tid >> 4, tc = tid & 15;
    float acc[4][4];
#pragma unroll
    for (int i = 0; i < 4; i++)
#pragma unroll
        for (int j = 0; j < 4; j++) acc[i][j] = 0.f;

    for (int k0 = 0; k0 < K; k0 += 64) {
        for (int i = tid; i < 64 * 64; i += 256) {
            int r = i >> 6, c = i & 63;
            int gr = row0 + r;
            xs[r][c] = (gr < NN) ? A[(size_t)gr * K + k0 + c] : 0.f;
            ws[r][c] = B[(size_t)(k0 + r) * ldb + col0 + c];
        }
        __syncthreads();
#pragma unroll
        for (int k = 0; k < 64; k++) {
            float a[4], b[4];
#pragma unroll
            for (int i = 0; i < 4; i++) a[i] = xs[tr * 4 + i][k];
#pragma unroll
            for (int j = 0; j < 4; j++) b[j] = ws[k][tc * 4 + j];
#pragma unroll
            for (int i = 0; i < 4; i++)
#pragma unroll
                for (int j = 0; j < 4; j++) acc[i][j] += a[i] * b[j];
        }
        __syncthreads();
    }
#pragma unroll
    for (int i = 0; i < 4; i++) {
        int gr = row0 + tr * 4 + i;
        if (gr < NN) {
#pragma unroll
            for (int j = 0; j < 4; j++)
                C[(size_t)gr * ldb + col0 + tc * 4 + j] = acc[i][j];
        }
    }
}

__global__ void gemm1_kernel(const float* __restrict__ A, const float* __restrict__ B) {
    gemm_body(A, B, g_h1, 64, 256);     // x[N,64] @ W1[64,256] -> h1
}
__global__ void gemm2_kernel(const float* __restrict__ B) {
    gemm_body(g_x2, B, g_h1, 256, 64);  // x2[N,256] @ W2[256,64] -> h2 (reuse g_h1)
}

// ---------------- attention logit vectors: al_s/al_d per node ----------------
__global__ void attn_kernel(const float* __restrict__ a_src,
                            const float* __restrict__ a_dst, int heads) {
    int warp = (blockIdx.x * blockDim.x + threadIdx.x) >> 5;
    int lane = threadIdx.x & 31;
    if (warp >= NN) return;
    const float* row = &g_h1[(size_t)warp * heads * 64];
    for (int h = 0; h < heads; h++) {
        float v1 = row[h * 64 + lane], v2 = row[h * 64 + 32 + lane];
        float ss = v1 * a_src[h * 64 + lane] + v2 * a_src[h * 64 + 32 + lane];
        float sd = v1 * a_dst[h * 64 + lane] + v2 * a_dst[h * 64 + 32 + lane];
#pragma unroll
        for (int o = 16; o; o >>= 1) {
            ss += __shfl_xor_sync(0xffffffffu, ss, o);
            sd += __shfl_xor_sync(0xffffffffu, sd, o);
        }
        if (lane == 0) {
            g_als[warp * heads + h] = ss;
            g_ald[warp * heads + h] = sd;
        }
    }
}

// ---------------- CSR build (edge_index delivered as int32) ----------------
__global__ void count_kernel(const int* __restrict__ ei) {
    int i = blockIdx.x * blockDim.x + threadIdx.x;
    if (i < NE) {
        int d = ei[NE + i];
        atomicAdd(&g_deg[d], 1);
    }
}

__global__ void scan_kernel() {
    __shared__ int wsum[32];
    __shared__ int s_carry;
    int t = threadIdx.x, lane = t & 31, wid = t >> 5;
    if (t == 0) s_carry = 0;
    __syncthreads();
    for (int base = 0; base < NN; base += 1024) {
        int i = base + t;
        int v = (i < NN) ? g_deg[i] + 1 : 0;   // +1 self loop
        int x = v;
#pragma unroll
        for (int o = 1; o < 32; o <<= 1) {
            int y = __shfl_up_sync(0xffffffffu, x, o);
            if (lane >= o) x += y;
        }
        if (lane == 31) wsum[wid] = x;
        __syncthreads();
        if (wid == 0) {
            int w = wsum[lane];
#pragma unroll
            for (int o = 1; o < 32; o <<= 1) {
                int y = __shfl_up_sync(0xffffffffu, w, o);
                if (lane >= o) w += y;
            }
            wsum[lane] = w;
        }
        __syncthreads();
        int warpoff = wid ? wsum[wid - 1] : 0;
        int excl = s_carry + warpoff + x - v;
        if (i < NN) { g_starts[i] = excl; g_cursor[i] = excl; }
        int total = wsum[31];
        __syncthreads();
        if (t == 0) s_carry += total;
        __syncthreads();
    }
    if (threadIdx.x == 0) g_starts[NN] = s_carry;
}

__global__ void scatter_kernel(const int* __restrict__ ei) {
    int i = blockIdx.x * blockDim.x + threadIdx.x;
    if (i < NT) {
        int s, d;
        if (i < NE) { s = ei[i]; d = ei[NE + i]; }
        else        { s = i - NE; d = s; }
        int p = atomicAdd(&g_cursor[d], 1);
        g_srcs[p] = s;
    }
}

// ---------------- layer 1 aggregation: warp per dst node, 4 heads x 64 ----------------
__global__ void agg1_kernel(const float* __restrict__ b1) {
    int warp = (blockIdx.x * blockDim.x + threadIdx.x) >> 5;
    int lane = threadIdx.x & 31;
    if (warp >= NN) return;
    int e0 = g_starts[warp], e1 = g_starts[warp + 1];
    float4 ad = *(const float4*)&g_ald[warp * 4];

    float m0 = -1e30f, m1 = -1e30f, m2 = -1e30f, m3 = -1e30f;
    for (int i = e0 + lane; i < e1; i += 32) {
        int s = g_srcs[i];
        float4 as = *(const float4*)&g_als[s * 4];
        float v0 = as.x + ad.x; v0 = v0 > 0.f ? v0 : 0.2f * v0;
        float v1 = as.y + ad.y; v1 = v1 > 0.f ? v1 : 0.2f * v1;
        float v2 = as.z + ad.z; v2 = v2 > 0.f ? v2 : 0.2f * v2;
        float v3 = as.w + ad.w; v3 = v3 > 0.f ? v3 : 0.2f * v3;
        float4 ev; ev.x = v0; ev.y = v1; ev.z = v2; ev.w = v3;
        *(float4*)&g_escr[(size_t)i * 4] = ev;
        m0 = fmaxf(m0, v0); m1 = fmaxf(m1, v1);
        m2 = fmaxf(m2, v2); m3 = fmaxf(m3, v3);
    }
#pragma unroll
    for (int o = 16; o; o >>= 1) {
        m0 = fmaxf(m0, __shfl_xor_sync(0xffffffffu, m0, o));
        m1 = fmaxf(m1, __shfl_xor_sync(0xffffffffu, m1, o));
        m2 = fmaxf(m2, __shfl_xor_sync(0xffffffffu, m2, o));
        m3 = fmaxf(m3, __shfl_xor_sync(0xffffffffu, m3, o));
    }
    float s0 = 0.f, s1 = 0.f, s2 = 0.f, s3 = 0.f;
    for (int i = e0 + lane; i < e1; i += 32) {
        float4 ev = *(float4*)&g_escr[(size_t)i * 4];
        ev.x = __expf(ev.x - m0); ev.y = __expf(ev.y - m1);
        ev.z = __expf(ev.z - m2); ev.w = __expf(ev.w - m3);
        *(float4*)&g_escr[(size_t)i * 4] = ev;
        s0 += ev.x; s1 += ev.y; s2 += ev.z; s3 += ev.w;
    }
#pragma unroll
    for (int o = 16; o; o >>= 1) {
        s0 += __shfl_xor_sync(0xffffffffu, s0, o);
        s1 += __shfl_xor_sync(0xffffffffu, s1, o);
        s2 += __shfl_xor_sync(0xffffffffu, s2, o);
        s3 += __shfl_xor_sync(0xffffffffu, s3, o);
    }
    float i0 = 1.f / (s0 + 1e-16f), i1 = 1.f / (s1 + 1e-16f);
    float i2 = 1.f / (s2 + 1e-16f), i3 = 1.f / (s3 + 1e-16f);

    float acc[8];
#pragma unroll
    for (int j = 0; j < 8; j++) acc[j] = 0.f;
    for (int i = e0; i < e1; i++) {
        int s = g_srcs[i];                       // uniform -> broadcast
        const float* hr = &g_h1[(size_t)s * 256];
        float4 ev = *(const float4*)&g_escr[(size_t)i * 4];
        float al[4] = {ev.x * i0, ev.y * i1, ev.z * i2, ev.w * i3};
#pragma unroll
        for (int j = 0; j < 8; j++)
            acc[j] += hr[j * 32 + lane] * al[j >> 1];
    }
#pragma unroll
    for (int j = 0; j < 8; j++) {
        int idx = j * 32 + lane;
        float v = acc[j] + b1[idx];
        g_x2[(size_t)warp * 256 + idx] = v > 0.f ? v : expm1f(v);  // ELU
    }
}

// ---------------- layer 2 aggregation: 1 head x 64 ----------------
__global__ void agg2_kernel(const float* __restrict__ b2) {
    int warp = (blockIdx.x * blockDim.x + threadIdx.x) >> 5;
    int lane = threadIdx.x & 31;
    if (warp >= NN) return;
    int e0 = g_starts[warp], e1 = g_starts[warp + 1];
    float ad = g_ald[warp];

    float mx = -1e30f;
    for (int i = e0 + lane; i < e1; i += 32) {
        int s = g_srcs[i];
        float v = g_als[s] + ad; v = v > 0.f ? v : 0.2f * v;
        g_escr[i] = v;
        mx = fmaxf(mx, v);
    }
#pragma unroll
    for (int o = 16; o; o >>= 1) mx = fmaxf(mx, __shfl_xor_sync(0xffffffffu, mx, o));
    float sm = 0.f;
    for (int i = e0 + lane; i < e1; i += 32) {
        float v = __expf(g_escr[i] - mx);
        g_escr[i] = v;
        sm += v;
    }
#pragma unroll
    for (int o = 16; o; o >>= 1) sm += __shfl_xor_sync(0xffffffffu, sm, o);
    float inv = 1.f / (sm + 1e-16f);

    float a0 = 0.f, a1 = 0.f;
    for (int i = e0; i < e1; i++) {
        int s = g_srcs[i];
        const float* hr = &g_h1[(size_t)s * 64];
        float al = g_escr[i] * inv;
        a0 += hr[lane] * al;
        a1 += hr[32 + lane] * al;
    }
    g_out2[(size_t)warp * 64 + lane]      = a0 + b2[lane];
    g_out2[(size_t)warp * 64 + 32 + lane] = a1 + b2[32 + lane];
}

// ---------------- pooling + classifier ----------------
__global__ void pool_kernel(const int* __restrict__ batch) {
    int i = blockIdx.x * blockDim.x + threadIdx.x;
    if (i >= NN * 64) return;
    int node = i >> 6, d = i & 63;
    int g = batch[node];
    atomicAdd(&g_pool[g * 64 + d], g_out2[i]);
    if (d == 0) atomicAdd(&g_cnt[g], 1.0f);
}

__global__ void cls_kernel(const float* __restrict__ Wc,
                           const float* __restrict__ bc,
                           float* __restrict__ out) {
    int g = blockIdx.x;             // 512 blocks, 128 threads
    __shared__ float emb[64];
    float c = fmaxf(g_cnt[g], 1.f);
    if (threadIdx.x < 64) emb[threadIdx.x] = g_pool[g * 64 + threadIdx.x] / c;
    __syncthreads();
    int cc = threadIdx.x;
    if (cc < NCLS) {
        float s = bc[cc];
#pragma unroll 16
        for (int d = 0; d < 64; d++) s += emb[d] * Wc[d * NCLS + cc];
        out[g * NCLS + cc] = s;
    }
}

// ---------------- launch ----------------
extern "C" void kernel_launch(void* const* d_in, const int* in_sizes, int n_in,
                              void* d_out, int out_size) {
    const float* x      = (const float*)d_in[0];
    const float* W1     = (const float*)d_in[1];
    const float* a_src1 = (const float*)d_in[2];
    const float* a_dst1 = (const float*)d_in[3];
    const float* b1     = (const float*)d_in[4];
    const float* W2     = (const float*)d_in[5];
    const float* a_src2 = (const float*)d_in[6];
    const float* a_dst2 = (const float*)d_in[7];
    const float* b2     = (const float*)d_in[8];
    const float* Wc     = (const float*)d_in[9];
    const float* bc     = (const float*)d_in[10];
    const int* ei       = (const int*)d_in[11];
    const int* batch    = (const int*)d_in[12];
    float* out = (float*)d_out;

    zero_kernel<<<(NN + 255) / 256, 256>>>();

    // CSR build (independent of GEMM path)
    count_kernel<<<(NE + 255) / 256, 256>>>(ei);
    scan_kernel<<<1, 1024>>>();
    scatter_kernel<<<(NT + 255) / 256, 256>>>(ei);

    // layer 1
    dim3 g1((NN + 63) / 64, 4);
    gemm1_kernel<<<g1, 256>>>(x, W1);
    attn_kernel<<<(NN * 32 + 255) / 256, 256>>>(a_src1, a_dst1, 4);
    agg1_kernel<<<(NN * 32 + 255) / 256, 256>>>(b1);

    // layer 2
    dim3 g2((NN + 63) / 64, 1);
    gemm2_kernel<<<g2, 256>>>(W2);
    attn_kernel<<<(NN * 32 + 255) / 256, 256>>>(a_src2, a_dst2, 1);
    agg2_kernel<<<(NN * 32 + 255) / 256, 256>>>(b2);

    // pooling + classifier
    pool_kernel<<<(NN * 64 + 255) / 256, 256>>>(batch);
    cls_kernel<<<NGRAPH, 128>>>(Wc, bc, out);
}

// round 3
// speedup vs baseline: 1.2988x; 1.2988x over previous
#include <cuda_runtime.h>
#include <math.h>

#define NN 50000
#define NE 800000
#define NT 850000     // NE + NN self loops
#define NGRAPH 512
#define NCLS 120

#define GB1X 782                 // ceil(NN/64)
#define GB1  (GB1X * 4)          // gemm1 tiles (4 head-column blocks)
#define CNTB 3125                // ceil(NE/256)
#define NODB 196                 // ceil(NN/256)
#define GRID_A (GB1 + CNTB + NODB)

#define SCAN_B   200
#define SCAN_SEG 250             // 200*250 == NN exactly

// ---------------- device scratch (no allocations allowed) ----------------
__device__ __align__(16) float g_h1[(size_t)NN * 256];  // layer1 feats / layer2 h2
__device__ __align__(16) float g_x2[(size_t)NN * 256];  // elu(layer1 out)
__device__ __align__(16) float g_als[NN * 4];
__device__ __align__(16) float g_ald[NN * 4];
__device__ __align__(16) float g_escr[(size_t)NT * 4];
__device__ int   g_deg[NN];          // invariant: all-zero at launch entry (reset by scan3)
__device__ int   g_starts[NN + 1];
__device__ int   g_cursor[NN];
__device__ int   g_srcs[NT];
__device__ int   g_bsum[SCAN_B];
__device__ int   g_boff[SCAN_B];
__device__ float g_pool[NGRAPH * 64];  // invariant: zero at entry (reset by cls)
__device__ float g_cnt[NGRAPH];        // invariant: zero at entry (reset by cls)

// ---------------- fused GEMM tile + attention-logit epilogue ----------------
// C[row0..row0+63][col0..col0+63] = A[.., K] @ B[K, ldb]; also writes
// g_als/g_ald for this tile's rows using asrc/adst (64 floats for this head).
__device__ __forceinline__ void gemm_attn_tile(
    const float* __restrict__ A, const float* __restrict__ B,
    float* __restrict__ C, int K, int ldb, int row0, int col0,
    const float* __restrict__ asrc, const float* __restrict__ adst,
    int head, int hstride)
{
    __shared__ __align__(16) float xsT[64][68];   // transposed A tile: [k][row]
    __shared__ __align__(16) float ws[64][68];    // B tile: [k][col]
    int tid = threadIdx.x;                 // 256 threads
    int tr = tid >> 4, tc = tid & 15;
    float acc[4][4];
#pragma unroll
    for (int i = 0; i < 4; i++)
#pragma unroll
        for (int j = 0; j < 4; j++) acc[i][j] = 0.f;

    for (int k0 = 0; k0 < K; k0 += 64) {
#pragma unroll
        for (int it = 0; it < 4; it++) {
            int v = it * 256 + tid;        // 0..1023 float4 slots
            int r = v >> 4, c4 = v & 15;
            int gr = row0 + r;
            float4 av = (gr < NN) ? *(const float4*)&A[(size_t)gr * K + k0 + c4 * 4]
                                  : make_float4(0.f, 0.f, 0.f, 0.f);
            xsT[c4 * 4 + 0][r] = av.x;
            xsT[c4 * 4 + 1][r] = av.y;
            xsT[c4 * 4 + 2][r] = av.z;
            xsT[c4 * 4 + 3][r] = av.w;
            float4 bv = *(const float4*)&B[(size_t)(k0 + r) * ldb + col0 + c4 * 4];
            *(float4*)&ws[r][c4 * 4] = bv;
        }
        __syncthreads();
#pragma unroll 8
        for (int k = 0; k < 64; k++) {
            float4 a4 = *(const float4*)&xsT[k][tr * 4];
            float4 b4 = *(const float4*)&ws[k][tc * 4];
            float a[4] = {a4.x, a4.y, a4.z, a4.w};
            float b[4] = {b4.x, b4.y, b4.z, b4.w};
#pragma unroll
            for (int i = 0; i < 4; i++)
#pragma unroll
                for (int j = 0; j < 4; j++) acc[i][j] += a[i] * b[j];
        }
        __syncthreads();
    }

    // store C tile
#pragma unroll
    for (int i = 0; i < 4; i++) {
        int gr = row0 + tr * 4 + i;
        if (gr < NN) {
            float4 cv = make_float4(acc[i][0], acc[i][1], acc[i][2], acc[i][3]);
            *(float4*)&C[(size_t)gr * ldb + col0 + tc * 4] = cv;
        }
    }

    // attention-logit epilogue: per-row dot with asrc/adst over this head's 64 cols
    float asv[4], adv[4];
#pragma unroll
    for (int j = 0; j < 4; j++) { asv[j] = asrc[tc * 4 + j]; adv[j] = adst[tc * 4 + j]; }
#pragma unroll
    for (int i = 0; i < 4; i++) {
        float ss = 0.f, sd = 0.f;
#pragma unroll
        for (int j = 0; j < 4; j++) { ss += acc[i][j] * asv[j]; sd += acc[i][j] * adv[j]; }
#pragma unroll
        for (int o = 1; o < 16; o <<= 1) {
            ss += __shfl_xor_sync(0xffffffffu, ss, o);
            sd += __shfl_xor_sync(0xffffffffu, sd, o);
        }
        int gr = row0 + tr * 4 + i;
        if (tc == 0 && gr < NN) {
            g_als[gr * hstride + head] = ss;
            g_ald[gr * hstride + head] = sd;
        }
    }
}

// ---------------- K_a: gemm1(+attn1 epi) || edge histogram || graph counts ----------------
__global__ void __launch_bounds__(256) Ka_kernel(
    const float* __restrict__ x, const float* __restrict__ W1,
    const float* __restrict__ a_src1, const float* __restrict__ a_dst1,
    const int* __restrict__ ei, const int* __restrict__ batch)
{
    int b = blockIdx.x;
    if (b < GB1) {
        int row0 = (b >> 2) * 64;
        int head = b & 3;
        gemm_attn_tile(x, W1, g_h1, 64, 256, row0, head * 64,
                       a_src1 + head * 64, a_dst1 + head * 64, head, 4);
    } else if (b < GB1 + CNTB) {
        int i = (b - GB1) * 256 + threadIdx.x;
        if (i < NE) atomicAdd(&g_deg[ei[NE + i]], 1);
    } else {
        int i = (b - GB1 - CNTB) * 256 + threadIdx.x;
        if (i < NN) atomicAdd(&g_cnt[batch[i]], 1.0f);
    }
}

__global__ void __launch_bounds__(256) Kb_kernel(
    const float* __restrict__ W2,
    const float* __restrict__ a_src2, const float* __restrict__ a_dst2)
{
    gemm_attn_tile(g_x2, W2, g_h1, 256, 64, blockIdx.x * 64, 0,
                   a_src2, a_dst2, 0, 1);
}

// ---------------- 3-phase scan of (deg+1) ----------------
__global__ void scan1_kernel() {
    int b = blockIdx.x, t = threadIdx.x;
    int v = (t < SCAN_SEG) ? g_deg[b * SCAN_SEG + t] + 1 : 0;
#pragma unroll
    for (int o = 16; o; o >>= 1) v += __shfl_xor_sync(0xffffffffu, v, o);
    __shared__ int red[8];
    if ((t & 31) == 0) red[t >> 5] = v;
    __syncthreads();
    if (t == 0) {
        int s = 0;
#pragma unroll
        for (int k = 0; k < 8; k++) s += red[k];
        g_bsum[b] = s;
    }
}

__device__ __forceinline__ int block_incl_scan256(int v) {
    __shared__ int wsum[8];
    int lane = threadIdx.x & 31, wid = threadIdx.x >> 5;
    int x = v;
#pragma unroll
    for (int o = 1; o < 32; o <<= 1) {
        int y = __shfl_up_sync(0xffffffffu, x, o);
        if (lane >= o) x += y;
    }
    if (lane == 31) wsum[wid] = x;
    __syncthreads();
    if (wid == 0 && lane < 8) {
        int w = wsum[lane];
#pragma unroll
        for (int o = 1; o < 8; o <<= 1) {
            int y = __shfl_up_sync(0x000000ffu, w, o);
            if (lane >= o) w += y;
        }
        wsum[lane] = w;
    }
    __syncthreads();
    if (wid > 0) x += wsum[wid - 1];
    return x;
}

__global__ void scan2_kernel() {
    int t = threadIdx.x;
    int v = (t < SCAN_B) ? g_bsum[t] : 0;
    int inc = block_incl_scan256(v);
    if (t < SCAN_B) g_boff[t] = inc - v;
    if (t == SCAN_B - 1) g_starts[NN] = inc;
}

__global__ void scan3_kernel() {
    int b = blockIdx.x, t = threadIdx.x;
    int i = b * SCAN_SEG + t;
    int v = (t < SCAN_SEG) ? g_deg[i] + 1 : 0;
    int inc = block_incl_scan256(v);
    if (t < SCAN_SEG) {
        int excl = inc - v + g_boff[b];
        g_starts[i] = excl;
        g_cursor[i] = excl;
        g_deg[i] = 0;            // reset invariant for next replay
    }
}

__global__ void scatter_kernel(const int* __restrict__ ei) {
    int i = blockIdx.x * blockDim.x + threadIdx.x;
    if (i < NT) {
        int s, d;
        if (i < NE) { s = ei[i]; d = ei[NE + i]; }
        else        { s = i - NE; d = s; }
        int p = atomicAdd(&g_cursor[d], 1);
        g_srcs[p] = s;
    }
}

// ---------------- layer 1 aggregation: warp per dst node ----------------
__global__ void agg1_kernel(const float* __restrict__ b1) {
    int warp = (blockIdx.x * blockDim.x + threadIdx.x) >> 5;
    int lane = threadIdx.x & 31;
    if (warp >= NN) return;
    int e0 = g_starts[warp], e1 = g_starts[warp + 1];
    float4 ad = *(const float4*)&g_ald[warp * 4];

    float m0 = -1e30f, m1 = -1e30f, m2 = -1e30f, m3 = -1e30f;
    for (int i = e0 + lane; i < e1; i += 32) {
        int s = g_srcs[i];
        float4 as = *(const float4*)&g_als[s * 4];
        float v0 = as.x + ad.x; v0 = v0 > 0.f ? v0 : 0.2f * v0;
        float v1 = as.y + ad.y; v1 = v1 > 0.f ? v1 : 0.2f * v1;
        float v2 = as.z + ad.z; v2 = v2 > 0.f ? v2 : 0.2f * v2;
        float v3 = as.w + ad.w; v3 = v3 > 0.f ? v3 : 0.2f * v3;
        float4 ev; ev.x = v0; ev.y = v1; ev.z = v2; ev.w = v3;
        *(float4*)&g_escr[(size_t)i * 4] = ev;
        m0 = fmaxf(m0, v0); m1 = fmaxf(m1, v1);
        m2 = fmaxf(m2, v2); m3 = fmaxf(m3, v3);
    }
#pragma unroll
    for (int o = 16; o; o >>= 1) {
        m0 = fmaxf(m0, __shfl_xor_sync(0xffffffffu, m0, o));
        m1 = fmaxf(m1, __shfl_xor_sync(0xffffffffu, m1, o));
        m2 = fmaxf(m2, __shfl_xor_sync(0xffffffffu, m2, o));
        m3 = fmaxf(m3, __shfl_xor_sync(0xffffffffu, m3, o));
    }
    float s0 = 0.f, s1 = 0.f, s2 = 0.f, s3 = 0.f;
    for (int i = e0 + lane; i < e1; i += 32) {
        float4 ev = *(float4*)&g_escr[(size_t)i * 4];
        ev.x = __expf(ev.x - m0); ev.y = __expf(ev.y - m1);
        ev.z = __expf(ev.z - m2); ev.w = __expf(ev.w - m3);
        *(float4*)&g_escr[(size_t)i * 4] = ev;
        s0 += ev.x; s1 += ev.y; s2 += ev.z; s3 += ev.w;
    }
#pragma unroll
    for (int o = 16; o; o >>= 1) {
        s0 += __shfl_xor_sync(0xffffffffu, s0, o);
        s1 += __shfl_xor_sync(0xffffffffu, s1, o);
        s2 += __shfl_xor_sync(0xffffffffu, s2, o);
        s3 += __shfl_xor_sync(0xffffffffu, s3, o);
    }
    float i0 = 1.f / (s0 + 1e-16f), i1 = 1.f / (s1 + 1e-16f);
    float i2 = 1.f / (s2 + 1e-16f), i3 = 1.f / (s3 + 1e-16f);

    float acc[8];
#pragma unroll
    for (int j = 0; j < 8; j++) acc[j] = 0.f;
    for (int i = e0; i < e1; i++) {
        int s = g_srcs[i];                      // uniform -> broadcast
        const float* hr = &g_h1[(size_t)s * 256];
        float4 ev = *(const float4*)&g_escr[(size_t)i * 4];
        float al[4] = {ev.x * i0, ev.y * i1, ev.z * i2, ev.w * i3};
#pragma unroll
        for (int j = 0; j < 8; j++)
            acc[j] += hr[j * 32 + lane] * al[j >> 1];
    }
#pragma unroll
    for (int j = 0; j < 8; j++) {
        int idx = j * 32 + lane;
        float v = acc[j] + b1[idx];
        g_x2[(size_t)warp * 256 + idx] = v > 0.f ? v : expm1f(v);  // ELU
    }
}

// ---------------- layer 2 aggregation + fused global mean pool ----------------
__global__ void agg2_kernel(const float* __restrict__ b2, const int* __restrict__ batch) {
    int warp = (blockIdx.x * blockDim.x + threadIdx.x) >> 5;
    int lane = threadIdx.x & 31;
    if (warp >= NN) return;
    int e0 = g_starts[warp], e1 = g_starts[warp + 1];
    float ad = g_ald[warp];

    float mx = -1e30f;
    for (int i = e0 + lane; i < e1; i += 32) {
        int s = g_srcs[i];
        float v = g_als[s] + ad; v = v > 0.f ? v : 0.2f * v;
        g_escr[i] = v;
        mx = fmaxf(mx, v);
    }
#pragma unroll
    for (int o = 16; o; o >>= 1) mx = fmaxf(mx, __shfl_xor_sync(0xffffffffu, mx, o));
    float sm = 0.f;
    for (int i = e0 + lane; i < e1; i += 32) {
        float v = __expf(g_escr[i] - mx);
        g_escr[i] = v;
        sm += v;
    }
#pragma unroll
    for (int o = 16; o; o >>= 1) sm += __shfl_xor_sync(0xffffffffu, sm, o);
    float inv = 1.f / (sm + 1e-16f);

    float a0 = 0.f, a1 = 0.f;
    for (int i = e0; i < e1; i++) {
        int s = g_srcs[i];
        const float* hr = &g_h1[(size_t)s * 64];
        float al = g_escr[i] * inv;
        a0 += hr[lane] * al;
        a1 += hr[32 + lane] * al;
    }
    int g = batch[warp];
    atomicAdd(&g_pool[g * 64 + lane],      a0 + b2[lane]);
    atomicAdd(&g_pool[g * 64 + 32 + lane], a1 + b2[32 + lane]);
}

// ---------------- classifier (reads then resets pool/cnt) ----------------
__global__ void cls_kernel(const float* __restrict__ Wc,
                           const float* __restrict__ bc,
                           float* __restrict__ out) {
    int g = blockIdx.x;             // 512 blocks, 128 threads
    __shared__ float emb[64];
    float c = fmaxf(g_cnt[g], 1.f);
    if (threadIdx.x < 64) emb[threadIdx.x] = g_pool[g * 64 + threadIdx.x] / c;
    __syncthreads();
    if (threadIdx.x < 64) g_pool[g * 64 + threadIdx.x] = 0.f;   // reset invariant
    if (threadIdx.x == 64) g_cnt[g] = 0.f;
    int cc = threadIdx.x;
    if (cc < NCLS) {
        float s = bc[cc];
#pragma unroll 16
        for (int d = 0; d < 64; d++) s += emb[d] * Wc[d * NCLS + cc];
        out[g * NCLS + cc] = s;
    }
}

// ---------------- launch ----------------
extern "C" void kernel_launch(void* const* d_in, const int* in_sizes, int n_in,
                              void* d_out, int out_size) {
    const float* x      = (const float*)d_in[0];
    const float* W1     = (const float*)d_in[1];
    const float* a_src1 = (const float*)d_in[2];
    const float* a_dst1 = (const float*)d_in[3];
    const float* b1     = (const float*)d_in[4];
    const float* W2     = (const float*)d_in[5];
    const float* a_src2 = (const float*)d_in[6];
    const float* a_dst2 = (const float*)d_in[7];
    const float* b2     = (const float*)d_in[8];
    const float* Wc     = (const float*)d_in[9];
    const float* bc     = (const float*)d_in[10];
    const int* ei       = (const int*)d_in[11];
    const int* batch    = (const int*)d_in[12];
    float* out = (float*)d_out;

    Ka_kernel<<<GRID_A, 256>>>(x, W1, a_src1, a_dst1, ei, batch);
    scan1_kernel<<<SCAN_B, 256>>>();
    scan2_kernel<<<1, 256>>>();
    scan3_kernel<<<SCAN_B, 256>>>();
    scatter_kernel<<<(NT + 255) / 256, 256>>>(ei);
    agg1_kernel<<<(NN * 32 + 255) / 256, 256>>>(b1);
    Kb_kernel<<<GB1X, 256>>>(W2, a_src2, a_dst2);
    agg2_kernel<<<(NN * 32 + 255) / 256, 256>>>(b2, batch);
    cls_kernel<<<NGRAPH, 128>>>(Wc, bc, out);
}

// round 4
// speedup vs baseline: 1.3327x; 1.0261x over previous
#include <cuda_runtime.h>
#include <cuda_bf16.h>
#include <math.h>

#define NN 50000
#define NE 800000
#define NT 850000     // NE + NN self loops
#define NGRAPH 512
#define NCLS 120

#define GB1X 782                 // ceil(NN/64)
#define GB1  (GB1X * 4)          // gemm1 tiles (4 head-column blocks)
#define CNTB 3125                // ceil(NE/256)
#define NODB 196                 // ceil(NN/256)
#define GRID_A (GB1 + CNTB + NODB)

#define SCAN_B   200
#define SCAN_SEG 250             // 200*250 == NN exactly

// ---------------- device scratch (no allocations allowed) ----------------
__device__ __align__(16) __nv_bfloat16 g_h1b[(size_t)NN * 256]; // layer1 feats (bf16, gather-only)
__device__ __align__(16) __nv_bfloat16 g_h2b[(size_t)NN * 64];  // layer2 feats (bf16, gather-only)
__device__ __align__(16) float g_x2[(size_t)NN * 256];          // elu(layer1 out), fp32
__device__ __align__(16) float g_als[NN * 4];
__device__ __align__(16) float g_ald[NN * 4];
__device__ int   g_deg[NN];          // invariant: all-zero at entry (reset by scan3)
__device__ int   g_starts[NN + 1];
__device__ int   g_cursor[NN];
__device__ int   g_srcs[NT];
__device__ int   g_bsum[SCAN_B];
__device__ int   g_boff[SCAN_B];
__device__ float g_pool[NGRAPH * 64];  // invariant: zero at entry (reset by cls)
__device__ float g_cnt[NGRAPH];        // invariant: zero at entry (reset by cls)

// ---------------- fused GEMM tile + bf16 store + attention-logit epilogue ----------------
__device__ __forceinline__ void gemm_attn_tile(
    const float* __restrict__ A, const float* __restrict__ B,
    __nv_bfloat16* __restrict__ Cb, int K, int ldb, int row0, int col0,
    const float* __restrict__ asrc, const float* __restrict__ adst,
    int head, int hstride)
{
    __shared__ __align__(16) float xsT[64][68];   // transposed A tile: [k][row]
    __shared__ __align__(16) float ws[64][68];    // B tile: [k][col]
    int tid = threadIdx.x;                 // 256 threads
    int tr = tid >> 4, tc = tid & 15;
    float acc[4][4];
#pragma unroll
    for (int i = 0; i < 4; i++)
#pragma unroll
        for (int j = 0; j < 4; j++) acc[i][j] = 0.f;

    for (int k0 = 0; k0 < K; k0 += 64) {
#pragma unroll
        for (int it = 0; it < 4; it++) {
            int v = it * 256 + tid;        // 0..1023 float4 slots
            int r = v >> 4, c4 = v & 15;
            int gr = row0 + r;
            float4 av = (gr < NN) ? *(const float4*)&A[(size_t)gr * K + k0 + c4 * 4]
                                  : make_float4(0.f, 0.f, 0.f, 0.f);
            xsT[c4 * 4 + 0][r] = av.x;
            xsT[c4 * 4 + 1][r] = av.y;
            xsT[c4 * 4 + 2][r] = av.z;
            xsT[c4 * 4 + 3][r] = av.w;
            float4 bv = *(const float4*)&B[(size_t)(k0 + r) * ldb + col0 + c4 * 4];
            *(float4*)&ws[r][c4 * 4] = bv;
        }
        __syncthreads();
#pragma unroll 8
        for (int k = 0; k < 64; k++) {
            float4 a4 = *(const float4*)&xsT[k][tr * 4];
            float4 b4 = *(const float4*)&ws[k][tc * 4];
            float a[4] = {a4.x, a4.y, a4.z, a4.w};
            float b[4] = {b4.x, b4.y, b4.z, b4.w};
#pragma unroll
            for (int i = 0; i < 4; i++)
#pragma unroll
                for (int j = 0; j < 4; j++) acc[i][j] += a[i] * b[j];
        }
        __syncthreads();
    }

    // store C tile as bf16 (gathers read only bf16)
#pragma unroll
    for (int i = 0; i < 4; i++) {
        int gr = row0 + tr * 4 + i;
        if (gr < NN) {
            __nv_bfloat162 p0 = __float22bfloat162_rn(make_float2(acc[i][0], acc[i][1]));
            __nv_bfloat162 p1 = __float22bfloat162_rn(make_float2(acc[i][2], acc[i][3]));
            __nv_bfloat162* dst = (__nv_bfloat162*)&Cb[(size_t)gr * ldb + col0 + tc * 4];
            dst[0] = p0; dst[1] = p1;
        }
    }

    // attention-logit epilogue (fp32 accumulators -> fp32 logits)
    float asv[4], adv[4];
#pragma unroll
    for (int j = 0; j < 4; j++) { asv[j] = asrc[tc * 4 + j]; adv[j] = adst[tc * 4 + j]; }
#pragma unroll
    for (int i = 0; i < 4; i++) {
        float ss = 0.f, sd = 0.f;
#pragma unroll
        for (int j = 0; j < 4; j++) { ss += acc[i][j] * asv[j]; sd += acc[i][j] * adv[j]; }
#pragma unroll
        for (int o = 1; o < 16; o <<= 1) {
            ss += __shfl_xor_sync(0xffffffffu, ss, o);
            sd += __shfl_xor_sync(0xffffffffu, sd, o);
        }
        int gr = row0 + tr * 4 + i;
        if (tc == 0 && gr < NN) {
            g_als[gr * hstride + head] = ss;
            g_ald[gr * hstride + head] = sd;
        }
    }
}

// ---------------- K_a: gemm1(+attn1 epi) || edge histogram || graph counts ----------------
__global__ void __launch_bounds__(256) Ka_kernel(
    const float* __restrict__ x, const float* __restrict__ W1,
    const float* __restrict__ a_src1, const float* __restrict__ a_dst1,
    const int* __restrict__ ei, const int* __restrict__ batch)
{
    int b = blockIdx.x;
    if (b < GB1) {
        int row0 = (b >> 2) * 64;
        int head = b & 3;
        gemm_attn_tile(x, W1, g_h1b, 64, 256, row0, head * 64,
                       a_src1 + head * 64, a_dst1 + head * 64, head, 4);
    } else if (b < GB1 + CNTB) {
        int i = (b - GB1) * 256 + threadIdx.x;
        if (i < NE) atomicAdd(&g_deg[ei[NE + i]], 1);
    } else {
        int i = (b - GB1 - CNTB) * 256 + threadIdx.x;
        if (i < NN) atomicAdd(&g_cnt[batch[i]], 1.0f);
    }
}

__global__ void __launch_bounds__(256) Kb_kernel(
    const float* __restrict__ W2,
    const float* __restrict__ a_src2, const float* __restrict__ a_dst2)
{
    gemm_attn_tile(g_x2, W2, g_h2b, 256, 64, blockIdx.x * 64, 0,
                   a_src2, a_dst2, 0, 1);
}

// ---------------- 3-phase scan of (deg+1) ----------------
__global__ void scan1_kernel() {
    int b = blockIdx.x, t = threadIdx.x;
    int v = (t < SCAN_SEG) ? g_deg[b * SCAN_SEG + t] + 1 : 0;
#pragma unroll
    for (int o = 16; o; o >>= 1) v += __shfl_xor_sync(0xffffffffu, v, o);
    __shared__ int red[8];
    if ((t & 31) == 0) red[t >> 5] = v;
    __syncthreads();
    if (t == 0) {
        int s = 0;
#pragma unroll
        for (int k = 0; k < 8; k++) s += red[k];
        g_bsum[b] = s;
    }
}

__device__ __forceinline__ int block_incl_scan256(int v) {
    __shared__ int wsum[8];
    int lane = threadIdx.x & 31, wid = threadIdx.x >> 5;
    int x = v;
#pragma unroll
    for (int o = 1; o < 32; o <<= 1) {
        int y = __shfl_up_sync(0xffffffffu, x, o);
        if (lane >= o) x += y;
    }
    if (lane == 31) wsum[wid] = x;
    __syncthreads();
    if (wid == 0 && lane < 8) {
        int w = wsum[lane];
#pragma unroll
        for (int o = 1; o < 8; o <<= 1) {
            int y = __shfl_up_sync(0x000000ffu, w, o);
            if (lane >= o) w += y;
        }
        wsum[lane] = w;
    }
    __syncthreads();
    if (wid > 0) x += wsum[wid - 1];
    return x;
}

__global__ void scan2_kernel() {
    int t = threadIdx.x;
    int v = (t < SCAN_B) ? g_bsum[t] : 0;
    int inc = block_incl_scan256(v);
    if (t < SCAN_B) g_boff[t] = inc - v;
    if (t == SCAN_B - 1) g_starts[NN] = inc;
}

__global__ void scan3_kernel() {
    int b = blockIdx.x, t = threadIdx.x;
    int i = b * SCAN_SEG + t;
    int v = (t < SCAN_SEG) ? g_deg[i] + 1 : 0;
    int inc = block_incl_scan256(v);
    if (t < SCAN_SEG) {
        int excl = inc - v + g_boff[b];
        g_starts[i] = excl;
        g_cursor[i] = excl;
        g_deg[i] = 0;            // reset invariant for next replay
    }
}

__global__ void scatter_kernel(const int* __restrict__ ei) {
    int i = blockIdx.x * blockDim.x + threadIdx.x;
    if (i < NT) {
        int s, d;
        if (i < NE) { s = ei[i]; d = ei[NE + i]; }
        else        { s = i - NE; d = s; }
        int p = atomicAdd(&g_cursor[d], 1);
        g_srcs[p] = s;
    }
}

__device__ __forceinline__ float lrelu(float v) { return v > 0.f ? v : 0.2f * v; }

// ---------------- layer 1 aggregation: warp/node, bf16 gather, 2-pass softmax ----------------
__global__ void agg1_kernel(const float* __restrict__ b1) {
    int warp = (blockIdx.x * blockDim.x + threadIdx.x) >> 5;
    int lane = threadIdx.x & 31;
    if (warp >= NN) return;
    int e0 = g_starts[warp], e1 = g_starts[warp + 1];
    float4 ad = *(const float4*)&g_ald[warp * 4];

    // pass 1: per-head max (lane-parallel over edges)
    float m0 = -1e30f, m1 = -1e30f, m2 = -1e30f, m3 = -1e30f;
    for (int i = e0 + lane; i < e1; i += 32) {
        int s = g_srcs[i];
        float4 as = *(const float4*)&g_als[s * 4];
        m0 = fmaxf(m0, lrelu(as.x + ad.x));
        m1 = fmaxf(m1, lrelu(as.y + ad.y));
        m2 = fmaxf(m2, lrelu(as.z + ad.z));
        m3 = fmaxf(m3, lrelu(as.w + ad.w));
    }
#pragma unroll
    for (int o = 16; o; o >>= 1) {
        m0 = fmaxf(m0, __shfl_xor_sync(0xffffffffu, m0, o));
        m1 = fmaxf(m1, __shfl_xor_sync(0xffffffffu, m1, o));
        m2 = fmaxf(m2, __shfl_xor_sync(0xffffffffu, m2, o));
        m3 = fmaxf(m3, __shfl_xor_sync(0xffffffffu, m3, o));
    }

    // per-lane head selection: lane handles features [lane*8, lane*8+8) -> head = lane>>3
    int hq = lane >> 3;
    float mq  = hq == 0 ? m0 : hq == 1 ? m1 : hq == 2 ? m2 : m3;
    float adq = hq == 0 ? ad.x : hq == 1 ? ad.y : hq == 2 ? ad.z : ad.w;

    // pass 2: serial over edges; unnormalized weighted accumulate.
    // every lane walks all edges, so its private sum IS the head denominator.
    float acc[8];
#pragma unroll
    for (int j = 0; j < 8; j++) acc[j] = 0.f;
    float ssum = 0.f;
    for (int i = e0; i < e1; i++) {
        int s = g_srcs[i];                         // uniform -> broadcast
        float4 as = *(const float4*)&g_als[s * 4];
        float asq = hq == 0 ? as.x : hq == 1 ? as.y : hq == 2 ? as.z : as.w;
        float w = __expf(lrelu(asq + adq) - mq);
        ssum += w;
        uint4 hv = *(const uint4*)(g_h1b + (size_t)s * 256 + lane * 8);
        float2 f0 = __bfloat1622float2(*(__nv_bfloat162*)&hv.x);
        float2 f1 = __bfloat1622float2(*(__nv_bfloat162*)&hv.y);
        float2 f2 = __bfloat1622float2(*(__nv_bfloat162*)&hv.z);
        float2 f3 = __bfloat1622float2(*(__nv_bfloat162*)&hv.w);
        acc[0] += w * f0.x; acc[1] += w * f0.y;
        acc[2] += w * f1.x; acc[3] += w * f1.y;
        acc[4] += w * f2.x; acc[5] += w * f2.y;
        acc[6] += w * f3.x; acc[7] += w * f3.y;
    }
    float inv = 1.f / (ssum + 1e-16f);

    float4 bva = *(const float4*)&b1[lane * 8];
    float4 bvb = *(const float4*)&b1[lane * 8 + 4];
    float bv[8] = {bva.x, bva.y, bva.z, bva.w, bvb.x, bvb.y, bvb.z, bvb.w};
    float o0[8];
#pragma unroll
    for (int j = 0; j < 8; j++) {
        float v = acc[j] * inv + bv[j];
        o0[j] = v > 0.f ? v : expm1f(v);           // ELU
    }
    float* dst = &g_x2[(size_t)warp * 256 + lane * 8];
    *(float4*)dst       = make_float4(o0[0], o0[1], o0[2], o0[3]);
    *(float4*)(dst + 4) = make_float4(o0[4], o0[5], o0[6], o0[7]);
}

// ---------------- layer 2 aggregation + fused global mean pool ----------------
__global__ void agg2_kernel(const float* __restrict__ b2, const int* __restrict__ batch) {
    int warp = (blockIdx.x * blockDim.x + threadIdx.x) >> 5;
    int lane = threadIdx.x & 31;
    if (warp >= NN) return;
    int e0 = g_starts[warp], e1 = g_starts[warp + 1];
    float ad = g_ald[warp];

    float mx = -1e30f;
    for (int i = e0 + lane; i < e1; i += 32) {
        int s = g_srcs[i];
        mx = fmaxf(mx, lrelu(g_als[s] + ad));
    }
#pragma unroll
    for (int o = 16; o; o >>= 1) mx = fmaxf(mx, __shfl_xor_sync(0xffffffffu, mx, o));

    float a0 = 0.f, a1 = 0.f, ssum = 0.f;
    for (int i = e0; i < e1; i++) {
        int s = g_srcs[i];
        float w = __expf(lrelu(g_als[s] + ad) - mx);
        ssum += w;
        unsigned hv = *(const unsigned*)(g_h2b + (size_t)s * 64 + lane * 2);
        float2 f = __bfloat1622float2(*(__nv_bfloat162*)&hv);
        a0 += w * f.x; a1 += w * f.y;
    }
    float inv = 1.f / (ssum + 1e-16f);
    int g = batch[warp];
    atomicAdd(&g_pool[g * 64 + lane * 2],     a0 * inv + b2[lane * 2]);
    atomicAdd(&g_pool[g * 64 + lane * 2 + 1], a1 * inv + b2[lane * 2 + 1]);
}

// ---------------- classifier (reads then resets pool/cnt) ----------------
__global__ void cls_kernel(const float* __restrict__ Wc,
                           const float* __restrict__ bc,
                           float* __restrict__ out) {
    int g = blockIdx.x;             // 512 blocks, 128 threads
    __shared__ float emb[64];
    float c = fmaxf(g_cnt[g], 1.f);
    if (threadIdx.x < 64) emb[threadIdx.x] = g_pool[g * 64 + threadIdx.x] / c;
    __syncthreads();
    if (threadIdx.x < 64) g_pool[g * 64 + threadIdx.x] = 0.f;   // reset invariant
    if (threadIdx.x == 64) g_cnt[g] = 0.f;
    int cc = threadIdx.x;
    if (cc < NCLS) {
        float s = bc[cc];
#pragma unroll 16
        for (int d = 0; d < 64; d++) s += emb[d] * Wc[d * NCLS + cc];
        out[g * NCLS + cc] = s;
    }
}

// ---------------- launch ----------------
extern "C" void kernel_launch(void* const* d_in, const int* in_sizes, int n_in,
                              void* d_out, int out_size) {
    const float* x      = (const float*)d_in[0];
    const float* W1     = (const float*)d_in[1];
    const float* a_src1 = (const float*)d_in[2];
    const float* a_dst1 = (const float*)d_in[3];
    const float* b1     = (const float*)d_in[4];
    const float* W2     = (const float*)d_in[5];
    const float* a_src2 = (const float*)d_in[6];
    const float* a_dst2 = (const float*)d_in[7];
    const float* b2     = (const float*)d_in[8];
    const float* Wc     = (const float*)d_in[9];
    const float* bc     = (const float*)d_in[10];
    const int* ei       = (const int*)d_in[11];
    const int* batch    = (const int*)d_in[12];
    float* out = (float*)d_out;

    Ka_kernel<<<GRID_A, 256>>>(x, W1, a_src1, a_dst1, ei, batch);
    scan1_kernel<<<SCAN_B, 256>>>();
    scan2_kernel<<<1, 256>>>();
    scan3_kernel<<<SCAN_B, 256>>>();
    scatter_kernel<<<(NT + 255) / 256, 256>>>(ei);
    agg1_kernel<<<(NN * 32 + 255) / 256, 256>>>(b1);
    Kb_kernel<<<GB1X, 256>>>(W2, a_src2, a_dst2);
    agg2_kernel<<<(NN * 32 + 255) / 256, 256>>>(b2, batch);
    cls_kernel<<<NGRAPH, 128>>>(Wc, bc, out);
}

// round 5
// speedup vs baseline: 1.5862x; 1.1902x over previous
#include <cuda_runtime.h>
#include <cuda_bf16.h>
#include <math.h>

#define NN 50000
#define NE 800000
#define NT 850000     // NE + NN self loops
#define NGRAPH 512
#define NCLS 120

#define MT1 391                  // ceil(NN/128)
#define GB1 (MT1 * 2)            // gemm1 tiles: 2 col-blocks of 128
#define CNTB 3125                // ceil(NE/256)
#define NODB 196                 // ceil(NN/256)
#define GRID_A (GB1 + CNTB + NODB)

#define SCAN_B   200
#define SCAN_SEG 250             // 200*250 == NN exactly

// ---------------- device scratch (no allocations allowed) ----------------
__device__ __align__(16) __nv_bfloat16 g_h1b[(size_t)NN * 256]; // layer1 feats (bf16)
__device__ __align__(16) __nv_bfloat16 g_h2b[(size_t)NN * 64];  // layer2 feats (bf16)
__device__ __align__(16) float g_x2[(size_t)NN * 256];          // elu(layer1 out), fp32
__device__ __align__(16) float g_als[NN * 4];
__device__ __align__(16) float g_ald[NN * 4];
__device__ int   g_deg[NN];          // invariant: all-zero at entry (reset by scan3)
__device__ int   g_starts[NN + 1];
__device__ int   g_cursor[NN];
__device__ int   g_srcs[NT];
__device__ int   g_bsum[SCAN_B];
__device__ float g_pool[NGRAPH * 64];  // invariant: zero at entry (reset by cls)
__device__ float g_cnt[NGRAPH];        // invariant: zero at entry (reset by cls)

// ---------------- packed f32x2 helpers ----------------
#define FMA2(d, a, b) asm("fma.rn.f32x2 %0, %1, %2, %0;" : "+l"(d) : "l"(a), "l"(b))
#define PACK2(d, x)   asm("mov.b64 %0, {%1, %1};" : "=l"(d) : "f"(x))
#define UNPACK2(lo, hi, d) asm("mov.b64 {%0, %1}, %2;" : "=f"(lo), "=f"(hi) : "l"(d))

// ---------------- fused GEMM tile (f32x2) + bf16 store + attn-logit epilogue ----------------
// 128-row M tile, NTILE-wide N tile, k-tiles of 64. 256 threads, 8 x (NTILE/16) per thread.
template<int KDIM, int NTILE>
__device__ __forceinline__ void gemm_attn_tile(
    const float* __restrict__ A, const float* __restrict__ B,
    __nv_bfloat16* __restrict__ Cb, int ldb, int row0, int col0,
    const float* __restrict__ asrc, const float* __restrict__ adst, int hstride)
{
    constexpr int TC = NTILE / 16;     // cols per thread: 8 or 4
    constexpr int NP = TC / 2;         // f32x2 pairs per thread
    constexpr int BF4 = NTILE / 4;     // float4 per B row
    constexpr int BITERS = 64 * BF4 / 256;
    extern __shared__ float smem_dyn[];
    float* xs = smem_dyn;              // [128][64] row-major (m, k)
    float* ws = smem_dyn + 128 * 64;   // [64][NTILE] (k, col)

    int tid = threadIdx.x;             // 256
    int tr = tid >> 4, tc = tid & 15;

    unsigned long long acc[8][NP];
#pragma unroll
    for (int i = 0; i < 8; i++)
#pragma unroll
        for (int p = 0; p < NP; p++) acc[i][p] = 0ull;

    for (int k0 = 0; k0 < KDIM; k0 += 64) {
#pragma unroll
        for (int it = 0; it < 8; it++) {       // A: 128x64 floats
            int v = it * 256 + tid;
            int r = v >> 4, c4 = v & 15;
            int gr = row0 + r;
            float4 av = (gr < NN) ? *(const float4*)&A[(size_t)gr * KDIM + k0 + c4 * 4]
                                  : make_float4(0.f, 0.f, 0.f, 0.f);
            *(float4*)&xs[r * 64 + c4 * 4] = av;
        }
#pragma unroll
        for (int it = 0; it < BITERS; it++) {  // B: 64xNTILE floats
            int v = it * 256 + tid;
            int r = v / BF4, c4 = v % BF4;
            *(float4*)&ws[r * NTILE + c4 * 4] =
                *(const float4*)&B[(size_t)(k0 + r) * ldb + col0 + c4 * 4];
        }
        __syncthreads();
#pragma unroll 4
        for (int k = 0; k < 64; k++) {
            float a[8];
#pragma unroll
            for (int i = 0; i < 8; i++) a[i] = xs[(tr * 8 + i) * 64 + k];
            unsigned long long bb[NP];
#pragma unroll
            for (int p = 0; p < NP; p += 2) {
                ulonglong2 bv = *(const ulonglong2*)&ws[k * NTILE + tc * TC + 2 * p];
                bb[p] = bv.x; bb[p + 1] = bv.y;
            }
#pragma unroll
            for (int i = 0; i < 8; i++) {
                unsigned long long aa;
                PACK2(aa, a[i]);
#pragma unroll
                for (int p = 0; p < NP; p++) FMA2(acc[i][p], aa, bb[p]);
            }
        }
        __syncthreads();
    }

    // epilogue: bf16 store + attention logits
    float asv[TC], adv[TC];
#pragma unroll
    for (int j = 0; j < TC; j++) {
        asv[j] = asrc[col0 + tc * TC + j];
        adv[j] = adst[col0 + tc * TC + j];
    }
    constexpr int GRP = 64 / TC;       // lanes covering one head: 8 or 16
#pragma unroll
    for (int i = 0; i < 8; i++) {
        int gr = row0 + tr * 8 + i;
        float fv[TC];
#pragma unroll
        for (int p = 0; p < NP; p++) UNPACK2(fv[2 * p], fv[2 * p + 1], acc[i][p]);
        float ss = 0.f, sd = 0.f;
#pragma unroll
        for (int j = 0; j < TC; j++) { ss += fv[j] * asv[j]; sd += fv[j] * adv[j]; }
        if (gr < NN) {
#pragma unroll
            for (int p = 0; p < NP; p++)
                *(__nv_bfloat162*)&Cb[(size_t)gr * ldb + col0 + tc * TC + 2 * p] =
                    __floats2bfloat162_rn(fv[2 * p], fv[2 * p + 1]);
        }
#pragma unroll
        for (int o = 1; o < GRP; o <<= 1) {
            ss += __shfl_xor_sync(0xffffffffu, ss, o);
            sd += __shfl_xor_sync(0xffffffffu, sd, o);
        }
        if ((tc & (GRP - 1)) == 0 && gr < NN) {
            int head = (col0 + tc * TC) >> 6;
            g_als[gr * hstride + head] = ss;
            g_ald[gr * hstride + head] = sd;
        }
    }
}

// ---------------- K_a: gemm1(+attn1 epi) || edge histogram || graph counts ----------------
__global__ void __launch_bounds__(256) Ka_kernel(
    const float* __restrict__ x, const float* __restrict__ W1,
    const float* __restrict__ a_src1, const float* __restrict__ a_dst1,
    const int* __restrict__ ei, const int* __restrict__ batch)
{
    int b = blockIdx.x;
    if (b < GB1) {
        int row0 = (b >> 1) * 128;
        int col0 = (b & 1) * 128;
        gemm_attn_tile<64, 128>(x, W1, g_h1b, 256, row0, col0, a_src1, a_dst1, 4);
    } else if (b < GB1 + CNTB) {
        int i = (b - GB1) * 256 + threadIdx.x;
        if (i < NE) atomicAdd(&g_deg[ei[NE + i]], 1);
    } else {
        int i = (b - GB1 - CNTB) * 256 + threadIdx.x;
        if (i < NN) atomicAdd(&g_cnt[batch[i]], 1.0f);
    }
}

__global__ void __launch_bounds__(256) Kb_kernel(
    const float* __restrict__ W2,
    const float* __restrict__ a_src2, const float* __restrict__ a_dst2)
{
    gemm_attn_tile<256, 64>(g_x2, W2, g_h2b, 64, blockIdx.x * 128, 0,
                            a_src2, a_dst2, 1);
}

// ---------------- scan of (deg+1): 2 kernels ----------------
__global__ void scan1_kernel() {
    int b = blockIdx.x, t = threadIdx.x;
    int v = (t < SCAN_SEG) ? g_deg[b * SCAN_SEG + t] + 1 : 0;
#pragma unroll
    for (int o = 16; o; o >>= 1) v += __shfl_xor_sync(0xffffffffu, v, o);
    __shared__ int red[8];
    if ((t & 31) == 0) red[t >> 5] = v;
    __syncthreads();
    if (t == 0) {
        int s = 0;
#pragma unroll
        for (int k = 0; k < 8; k++) s += red[k];
        g_bsum[b] = s;
    }
}

__device__ __forceinline__ int block_incl_scan256(int v) {
    __shared__ int wsum[8];
    int lane = threadIdx.x & 31, wid = threadIdx.x >> 5;
    int x = v;
#pragma unroll
    for (int o = 1; o < 32; o <<= 1) {
        int y = __shfl_up_sync(0xffffffffu, x, o);
        if (lane >= o) x += y;
    }
    if (lane == 31) wsum[wid] = x;
    __syncthreads();
    if (wid == 0 && lane < 8) {
        int w = wsum[lane];
#pragma unroll
        for (int o = 1; o < 8; o <<= 1) {
            int y = __shfl_up_sync(0x000000ffu, w, o);
            if (lane >= o) w += y;
        }
        wsum[lane] = w;
    }
    __syncthreads();
    if (wid > 0) x += wsum[wid - 1];
    return x;
}

// scan3: each block rescans the 200 block-sums locally (absorbs old scan2),
// then scans its own 250-node segment; also resets g_deg for the next replay.
__global__ void scan3_kernel() {
    __shared__ int soff[256];
    int b = blockIdx.x, t = threadIdx.x;
    int v2 = (t < SCAN_B) ? g_bsum[t] : 0;
    int inc2 = block_incl_scan256(v2);
    soff[t] = inc2;
    __syncthreads();
    int boff = b ? soff[b - 1] : 0;
    if (b == 0 && t == SCAN_B - 1) g_starts[NN] = inc2;   // grand total
    __syncthreads();

    int i = b * SCAN_SEG + t;
    int v = (t < SCAN_SEG) ? g_deg[i] + 1 : 0;
    int inc = block_incl_scan256(v);
    if (t < SCAN_SEG) {
        int excl = inc - v + boff;
        g_starts[i] = excl;
        g_cursor[i] = excl;
        g_deg[i] = 0;            // reset invariant
    }
}

__global__ void scatter_kernel(const int* __restrict__ ei) {
    int i = blockIdx.x * blockDim.x + threadIdx.x;
    if (i < NT) {
        int s, d;
        if (i < NE) { s = ei[i]; d = ei[NE + i]; }
        else        { s = i - NE; d = s; }
        int p = atomicAdd(&g_cursor[d], 1);
        g_srcs[p] = s;
    }
}

__device__ __forceinline__ float lrelu(float v) { return v > 0.f ? v : 0.2f * v; }

// ---------------- layer 1 aggregation: warp/node, bf16 gather, 2-pass softmax ----------------
__global__ void agg1_kernel(const float* __restrict__ b1) {
    int warp = (blockIdx.x * blockDim.x + threadIdx.x) >> 5;
    int lane = threadIdx.x & 31;
    if (warp >= NN) return;
    int e0 = g_starts[warp], e1 = g_starts[warp + 1];
    float4 ad = *(const float4*)&g_ald[warp * 4];

    // pass 1: per-head max (lane-parallel)
    float m0 = -1e30f, m1 = -1e30f, m2 = -1e30f, m3 = -1e30f;
    for (int i = e0 + lane; i < e1; i += 32) {
        int s = g_srcs[i];
        float4 as = *(const float4*)&g_als[s * 4];
        m0 = fmaxf(m0, lrelu(as.x + ad.x));
        m1 = fmaxf(m1, lrelu(as.y + ad.y));
        m2 = fmaxf(m2, lrelu(as.z + ad.z));
        m3 = fmaxf(m3, lrelu(as.w + ad.w));
    }
#pragma unroll
    for (int o = 16; o; o >>= 1) {
        m0 = fmaxf(m0, __shfl_xor_sync(0xffffffffu, m0, o));
        m1 = fmaxf(m1, __shfl_xor_sync(0xffffffffu, m1, o));
        m2 = fmaxf(m2, __shfl_xor_sync(0xffffffffu, m2, o));
        m3 = fmaxf(m3, __shfl_xor_sync(0xffffffffu, m3, o));
    }

    // lane handles features [lane*8, lane*8+8) -> head = lane>>3
    int hq = lane >> 3;
    float mq  = hq == 0 ? m0 : hq == 1 ? m1 : hq == 2 ? m2 : m3;
    float adq = hq == 0 ? ad.x : hq == 1 ? ad.y : hq == 2 ? ad.z : ad.w;

    // pass 2: serial over edges; per-lane private sum IS the head denominator.
    float acc[8];
#pragma unroll
    for (int j = 0; j < 8; j++) acc[j] = 0.f;
    float ssum = 0.f;
#pragma unroll 4
    for (int i = e0; i < e1; i++) {
        int s = g_srcs[i];                       // uniform -> broadcast
        float4 as = *(const float4*)&g_als[s * 4];
        float asq = hq == 0 ? as.x : hq == 1 ? as.y : hq == 2 ? as.z : as.w;
        float w = __expf(lrelu(asq + adq) - mq);
        ssum += w;
        uint4 hv = *(const uint4*)(g_h1b + (size_t)s * 256 + lane * 8);
        float2 f0 = __bfloat1622float2(*(__nv_bfloat162*)&hv.x);
        float2 f1 = __bfloat1622float2(*(__nv_bfloat162*)&hv.y);
        float2 f2 = __bfloat1622float2(*(__nv_bfloat162*)&hv.z);
        float2 f3 = __bfloat1622float2(*(__nv_bfloat162*)&hv.w);
        acc[0] += w * f0.x; acc[1] += w * f0.y;
        acc[2] += w * f1.x; acc[3] += w * f1.y;
        acc[4] += w * f2.x; acc[5] += w * f2.y;
        acc[6] += w * f3.x; acc[7] += w * f3.y;
    }
    float inv = 1.f / (ssum + 1e-16f);

    float4 bva = *(const float4*)&b1[lane * 8];
    float4 bvb = *(const float4*)&b1[lane * 8 + 4];
    float bv[8] = {bva.x, bva.y, bva.z, bva.w, bvb.x, bvb.y, bvb.z, bvb.w};
    float o0[8];
#pragma unroll
    for (int j = 0; j < 8; j++) {
        float v = acc[j] * inv + bv[j];
        o0[j] = v > 0.f ? v : expm1f(v);         // ELU
    }
    float* dst = &g_x2[(size_t)warp * 256 + lane * 8];
    *(float4*)dst       = make_float4(o0[0], o0[1], o0[2], o0[3]);
    *(float4*)(dst + 4) = make_float4(o0[4], o0[5], o0[6], o0[7]);
}

// ---------------- layer 2 aggregation + fused global mean pool ----------------
__global__ void agg2_kernel(const float* __restrict__ b2, const int* __restrict__ batch) {
    int warp = (blockIdx.x * blockDim.x + threadIdx.x) >> 5;
    int lane = threadIdx.x & 31;
    if (warp >= NN) return;
    int e0 = g_starts[warp], e1 = g_starts[warp + 1];
    float ad = g_ald[warp];

    float mx = -1e30f;
    for (int i = e0 + lane; i < e1; i += 32) {
        int s = g_srcs[i];
        mx = fmaxf(mx, lrelu(g_als[s] + ad));
    }
#pragma unroll
    for (int o = 16; o; o >>= 1) mx = fmaxf(mx, __shfl_xor_sync(0xffffffffu, mx, o));

    float a0 = 0.f, a1 = 0.f, ssum = 0.f;
#pragma unroll 4
    for (int i = e0; i < e1; i++) {
        int s = g_srcs[i];
        float w = __expf(lrelu(g_als[s] + ad) - mx);
        ssum += w;
        unsigned hv = *(const unsigned*)(g_h2b + (size_t)s * 64 + lane * 2);
        float2 f = __bfloat1622float2(*(__nv_bfloat162*)&hv);
        a0 += w * f.x; a1 += w * f.y;
    }
    float inv = 1.f / (ssum + 1e-16f);
    int g = batch[warp];
    atomicAdd(&g_pool[g * 64 + lane * 2],     a0 * inv + b2[lane * 2]);
    atomicAdd(&g_pool[g * 64 + lane * 2 + 1], a1 * inv + b2[lane * 2 + 1]);
}

// ---------------- classifier (reads then resets pool/cnt) ----------------
__global__ void cls_kernel(const float* __restrict__ Wc,
                           const float* __restrict__ bc,
                           float* __restrict__ out) {
    int g = blockIdx.x;             // 512 blocks, 128 threads
    __shared__ float emb[64];
    float c = fmaxf(g_cnt[g], 1.f);
    if (threadIdx.x < 64) emb[threadIdx.x] = g_pool[g * 64 + threadIdx.x] / c;
    __syncthreads();
    if (threadIdx.x < 64) g_pool[g * 64 + threadIdx.x] = 0.f;   // reset invariant
    if (threadIdx.x == 64) g_cnt[g] = 0.f;
    int cc = threadIdx.x;
    if (cc < NCLS) {
        float s = bc[cc];
#pragma unroll 16
        for (int d = 0; d < 64; d++) s += emb[d] * Wc[d * NCLS + cc];
        out[g * NCLS + cc] = s;
    }
}

// ---------------- launch ----------------
#define SMEM_KA ((128 * 64 + 64 * 128) * 4)   // 65536
#define SMEM_KB ((128 * 64 + 64 * 64) * 4)    // 49152

extern "C" void kernel_launch(void* const* d_in, const int* in_sizes, int n_in,
                              void* d_out, int out_size) {
    const float* x      = (const float*)d_in[0];
    const float* W1     = (const float*)d_in[1];
    const float* a_src1 = (const float*)d_in[2];
    const float* a_dst1 = (const float*)d_in[3];
    const float* b1     = (const float*)d_in[4];
    const float* W2     = (const float*)d_in[5];
    const float* a_src2 = (const float*)d_in[6];
    const float* a_dst2 = (const float*)d_in[7];
    const float* b2     = (const float*)d_in[8];
    const float* Wc     = (const float*)d_in[9];
    const float* bc     = (const float*)d_in[10];
    const int* ei       = (const int*)d_in[11];
    const int* batch    = (const int*)d_in[12];
    float* out = (float*)d_out;

    cudaFuncSetAttribute(Ka_kernel, cudaFuncAttributeMaxDynamicSharedMemorySize, SMEM_KA);
    cudaFuncSetAttribute(Kb_kernel, cudaFuncAttributeMaxDynamicSharedMemorySize, SMEM_KB);

    Ka_kernel<<<GRID_A, 256, SMEM_KA>>>(x, W1, a_src1, a_dst1, ei, batch);
    scan1_kernel<<<SCAN_B, 256>>>();
    scan3_kernel<<<SCAN_B, 256>>>();
    scatter_kernel<<<(NT + 255) / 256, 256>>>(ei);
    agg1_kernel<<<(NN * 32 + 255) / 256, 256>>>(b1);
    Kb_kernel<<<MT1, 256, SMEM_KB>>>(W2, a_src2, a_dst2);
    agg2_kernel<<<(NN * 32 + 255) / 256, 256>>>(b2, batch);
    cls_kernel<<<NGRAPH, 128>>>(Wc, bc, out);
}